// round 13
// baseline (speedup 1.0000x reference)
#include <cuda_runtime.h>
#include <cuda_bf16.h>
#include <mma.h>
#include <math.h>

// GRU: B=128, T=512, I=256, H=512. out = final h [1,128,512] fp32.
// Persistent kernel, 128 CTAs (4 batch x 32 j). Pipelined pre-phase computes
// x@W_ih^T for all t into g_xg (1 sync/iter, W_ih frags in regs). Main loop:
// h-projection only (wmma bf16 hi/lo 3-product), SMEM h staging, producer
// flags polled by every warp (no atomics), h_old in registers, 3 syncs/step.

using namespace nvcuda;

#define BATCH 128
#define TT    512
#define II    256
#define HH    512
#define GB    4
#define GJ    32
#define BC    32
#define JC    16
#define NCTA  128
#define NSYNC 32
#define NTHR  512

#define USTRIDE 264       // u16 per U row (256+8)
#define WHHS    520       // u16 per W_hh row (512+8)
#define WIHS    264       // u16 per W_ih row (256+8)

// SMEM byte offsets
#define SM_WHH_H 0                       // 48*520*2 = 49920
#define SM_WHH_L 49920                   // -> 99840
#define SM_UH1   99840                   // 32*264*2 = 16896
#define SM_UL1   116736
#define SM_UH0   133632
#define SM_UL0   150528
#define SM_DRED  167424                  // 48*1024 = 49152 (pre: 2x12 tiles)
#define SM_BS    216576                  // 96 f32
#define SMEM_BYTES 217088
// pre-phase temporaries (retired before their hosts' first use)
#define SM_WIH_H SM_UH1                  // 48*264*2 = 25344 (Uh1 + part Ul1)
#define SM_WIH_L SM_DRED                 // 25344 <= 49152

__device__ float          g_xg[(size_t)GJ*BATCH*TT*48];   // [gj][b][t][48]
__device__ unsigned short g_hsh[2][BATCH*HH];
__device__ unsigned short g_hsl[2][BATCH*HH];
__device__ __align__(128) unsigned int g_flags[GB][32];
__device__ unsigned int   g_cnt[GB*32];
__device__ unsigned int   g_ph [GB*32];

__device__ __forceinline__ float sigm(float x) {
    return 1.0f / (1.0f + __expf(-x));
}
__device__ __forceinline__ unsigned short bhi(float v) {
    return __bfloat16_as_ushort(__float2bfloat16(v));
}
__device__ __forceinline__ unsigned short blo(float v) {
    __nv_bfloat16 h = __float2bfloat16(v);
    return __bfloat16_as_ushort(__float2bfloat16(v - __bfloat162float(h)));
}

extern "C" __global__ void __launch_bounds__(NTHR, 1)
gru_persistent_kernel(const float* __restrict__ x,      // [B, T, I]
                      const float* __restrict__ W_ih,   // [3H, I]
                      const float* __restrict__ W_hh,   // [3H, H]
                      const float* __restrict__ b_ih,   // [3H]
                      const float* __restrict__ b_hh,   // [3H]
                      float* __restrict__ out)          // [1, B, H]
{
    extern __shared__ char smem[];
    unsigned short* WhhH = (unsigned short*)(smem + SM_WHH_H);
    unsigned short* WhhL = (unsigned short*)(smem + SM_WHH_L);
    unsigned short* Uh1  = (unsigned short*)(smem + SM_UH1);
    unsigned short* Ul1  = (unsigned short*)(smem + SM_UL1);
    unsigned short* Uh0  = (unsigned short*)(smem + SM_UH0);
    unsigned short* Ul0  = (unsigned short*)(smem + SM_UL0);
    unsigned short* WihH = (unsigned short*)(smem + SM_WIH_H);
    unsigned short* WihL = (unsigned short*)(smem + SM_WIH_L);
    float* Dred = (float*)(smem + SM_DRED);
    float* B_s  = (float*)(smem + SM_BS);

    const int tid = threadIdx.x;
    const int bx  = blockIdx.x;
    const int gb  = bx & (GB - 1);
    const int gj  = bx >> 2;
    const int b0  = gb * BC;
    const int j0  = gj * JC;

    unsigned base = 0;
    if (tid == 0) base = *((volatile unsigned*)&g_ph[gb * 32]);

    // ---- one-time: W_hh hi/lo (permanent), W_ih hi/lo (temp), biases ----
    for (int idx = tid; idx < 48 * 512; idx += NTHR) {
        int row = idx >> 9, col = idx & 511;
        int G = (row < 16) ? j0 + row
              : (row < 32) ? 512 + j0 + (row - 16)
                           : 1024 + j0 + (row - 32);
        float v = W_hh[G * HH + col];
        WhhH[row * WHHS + col] = bhi(v);
        WhhL[row * WHHS + col] = blo(v);
    }
    for (int idx = tid; idx < 48 * 256; idx += NTHR) {
        int row = idx >> 8, col = idx & 255;
        int G = (row < 16) ? j0 + row
              : (row < 32) ? 512 + j0 + (row - 16)
                           : 1024 + j0 + (row - 32);
        float v = W_ih[G * II + col];
        WihH[row * WIHS + col] = bhi(v);
        WihL[row * WIHS + col] = blo(v);
    }
    if (tid < 96) {
        int loc = tid % 48;
        int G = (loc < 16) ? j0 + loc
              : (loc < 32) ? 512 + j0 + (loc - 16)
                           : 1024 + j0 + (loc - 32);
        B_s[tid] = (tid < 48) ? b_hh[G] : b_ih[G];
    }
    __syncthreads();

    const int w  = tid >> 5;
    const int kh = w & 1;
    const int tau = w >> 1;
    const int ntileP = tau % 3;
    const int btileP = tau / 3;

    wmma::fragment<wmma::matrix_a, 16, 16, 16, __nv_bfloat16, wmma::row_major> fa_h, fa_l;
    wmma::fragment<wmma::matrix_b, 16, 16, 16, __nv_bfloat16, wmma::col_major> fb_h, fb_l;
    wmma::fragment<wmma::matrix_b, 16, 16, 16, __nv_bfloat16, wmma::col_major> fwh[8], fwl[8];
    wmma::fragment<wmma::accumulator, 16, 16, 16, float> facc, acc0, acc1, acc2;

    if (w < 12) {   // W_ih fragments live in registers for the whole pre-phase
        const __nv_bfloat16* Bh = (const __nv_bfloat16*)WihH + ntileP * 16 * WIHS;
        const __nv_bfloat16* Bl = (const __nv_bfloat16*)WihL + ntileP * 16 * WIHS;
        #pragma unroll
        for (int i = 0; i < 8; i++) {
            int ks = kh * 8 + i;
            wmma::load_matrix_sync(fwh[i], Bh + ks * 16, WIHS);
            wmma::load_matrix_sync(fwl[i], Bl + ks * 16, WIHS);
        }
    }
    __syncthreads();   // W_ih temps retired; Dred/Uh*/Ul* free

    // helper indices
    const int srow = tid >> 4;          // 0..31
    const int sk16 = (tid & 15) * 16;
    const int sk32 = (tid & 15) * 32;
    const int jj   = tid & 15;
    const int bb   = tid >> 4;          // 0..31
    const int btl  = bb >> 4;
    const int loc  = (bb & 15) * 16 + jj;

    const size_t xg_cta = (((size_t)gj * BATCH + b0 + bb) * TT) * 48;

    // ---- pipelined pre-phase: g_xg = x @ W_ih^T + b_ih, 1 sync/iter ----
    auto stage_x = [&](int t, int p) {
        unsigned short* DH = p ? Uh1 : Uh0;
        unsigned short* DL = p ? Ul1 : Ul0;
        const float* xs = x + ((size_t)(b0 + srow) * TT + t) * II + sk16;
        float vv[16];
        *(float4*)(vv + 0)  = *(const float4*)(xs + 0);
        *(float4*)(vv + 4)  = *(const float4*)(xs + 4);
        *(float4*)(vv + 8)  = *(const float4*)(xs + 8);
        *(float4*)(vv + 12) = *(const float4*)(xs + 12);
        unsigned hp[8], lp[8];
        #pragma unroll
        for (int k2 = 0; k2 < 8; k2++) {
            unsigned h0 = bhi(vv[2*k2]), h1 = bhi(vv[2*k2+1]);
            unsigned l0 = blo(vv[2*k2]), l1 = blo(vv[2*k2+1]);
            hp[k2] = h0 | (h1 << 16);
            lp[k2] = l0 | (l1 << 16);
        }
        uint4* dh = (uint4*)(DH + srow * USTRIDE + sk16);
        uint4* dl = (uint4*)(DL + srow * USTRIDE + sk16);
        dh[0] = make_uint4(hp[0], hp[1], hp[2], hp[3]);
        dh[1] = make_uint4(hp[4], hp[5], hp[6], hp[7]);
        dl[0] = make_uint4(lp[0], lp[1], lp[2], lp[3]);
        dl[1] = make_uint4(lp[4], lp[5], lp[6], lp[7]);
    };
    auto write_gxg = [&](int t) {
        const float* Dp = Dred + (t & 1) * 12 * 256;
        const size_t xb = xg_cta + (size_t)t * 48;
        #pragma unroll
        for (int g = 0; g < 3; g++) {
            float v = Dp[((btl * 3 + g) * 2 + 0) * 256 + loc]
                    + Dp[((btl * 3 + g) * 2 + 1) * 256 + loc]
                    + B_s[48 + g * 16 + jj];
            g_xg[xb + g * 16 + jj] = v;
        }
    };

    stage_x(0, 0);
    __syncthreads();
    for (int t = 0; t < TT; t++) {
        if (t > 0) write_gxg(t - 1);                 // reads Dred[(t-1)&1]
        if (t + 1 < TT) stage_x(t + 1, (t + 1) & 1); // writes buf[(t+1)&1]
        if (w < 12) {                                // mma(t): buf[t&1] -> Dred[t&1]
            wmma::fill_fragment(facc, 0.0f);
            const unsigned short* SH = (t & 1) ? Uh1 : Uh0;
            const unsigned short* SL = (t & 1) ? Ul1 : Ul0;
            const __nv_bfloat16* Ah = (const __nv_bfloat16*)SH + btileP * 16 * USTRIDE;
            const __nv_bfloat16* Al = (const __nv_bfloat16*)SL + btileP * 16 * USTRIDE;
            #pragma unroll
            for (int i = 0; i < 8; i++) {
                int ks = kh * 8 + i;
                wmma::load_matrix_sync(fa_h, Ah + ks * 16, USTRIDE);
                wmma::load_matrix_sync(fa_l, Al + ks * 16, USTRIDE);
                wmma::mma_sync(facc, fa_h, fwh[i], facc);
                wmma::mma_sync(facc, fa_h, fwl[i], facc);
                wmma::mma_sync(facc, fa_l, fwh[i], facc);
            }
            wmma::store_matrix_sync(Dred + ((t & 1) * 12 + tau * 2 + kh) * 256,
                                    facc, 16, wmma::mem_row_major);
        }
        __syncthreads();
    }
    write_gxg(TT - 1);

    // zero h0 planes (parity 0) for this CTA's tile; reset our flag
    for (int i = tid; i < BC * JC; i += NTHR) {
        int b = i >> 4, j = i & 15;
        int gi = (b0 + b) * HH + j0 + j;
        g_hsh[0][gi] = 0;
        g_hsl[0][gi] = 0;
    }
    if (tid == 0) *((volatile unsigned*)&g_flags[gb][gj]) = 0u;

    // init barrier (blocking, self-cleaning): resets + h0 visible group-wide
    __syncthreads();
    if (tid == 0) {
        __threadfence();
        if (atomicAdd(&g_cnt[gb * 32], 1u) == NSYNC - 1u) {
            g_cnt[gb * 32] = 0;
            __threadfence();
            *((volatile unsigned*)&g_ph[gb * 32]) = base + 1u;
        }
        while ((unsigned)(*((volatile unsigned*)&g_ph[gb * 32]) - base) < 1u) {
            __nanosleep(32);
        }
        __threadfence();
    }
    __syncthreads();

    // ---- main loop: h projection only, 3 syncs/step ----
    const int btile = w >> 3;           // 16 mma warps: 2 btile x 8 kw
    const int kw    = w & 7;
    const int lane  = tid & 31;
    const float bhr = B_s[jj];
    const float bhz = B_s[16 + jj];
    const float bhn = B_s[32 + jj];
    float hold = 0.0f;

    for (int t = 0; t < TT; t++) {
        const int rp = t & 1;
        const int wp = rp ^ 1;

        // prefetch x gates (no peer dependence)
        const size_t xb = xg_cta + (size_t)t * 48;
        float xr  = g_xg[xb + jj];
        float xz  = g_xg[xb + 16 + jj];
        float xnv = g_xg[xb + 32 + jj];

        // every warp polls all 32 producer flags, then stages its own rows
        {
            const volatile unsigned* fl = &g_flags[gb][0];
            for (;;) {
                unsigned v = fl[lane];
                if (!__any_sync(0xFFFFFFFFu, v < (unsigned)t)) break;
                __nanosleep(32);
            }
        }
        __threadfence();

        // stage h planes: cols 0-255 -> Uh1/Ul1, 256-511 -> Uh0/Ul0
        {
            const int goff = (b0 + srow) * HH + sk32;
            const uint4* sh = (const uint4*)(g_hsh[rp] + goff);
            const uint4* sl = (const uint4*)(g_hsl[rp] + goff);
            uint4 *dh, *dl;
            if (sk32 < 256) {
                dh = (uint4*)(Uh1 + srow * USTRIDE + sk32);
                dl = (uint4*)(Ul1 + srow * USTRIDE + sk32);
            } else {
                dh = (uint4*)(Uh0 + srow * USTRIDE + (sk32 - 256));
                dl = (uint4*)(Ul0 + srow * USTRIDE + (sk32 - 256));
            }
            dh[0] = sh[0]; dh[1] = sh[1]; dh[2] = sh[2]; dh[3] = sh[3];
            dl[0] = sl[0]; dl[1] = sl[1]; dl[2] = sl[2]; dl[3] = sl[3];
        }
        __syncthreads();

        // mma: 16 warps, warp = (btile, kw); 3 gates share A fragments
        {
            const __nv_bfloat16 *Ah, *Al;
            int ksl0;
            if (kw < 4) {
                Ah = (const __nv_bfloat16*)Uh1; Al = (const __nv_bfloat16*)Ul1;
                ksl0 = kw * 4;
            } else {
                Ah = (const __nv_bfloat16*)Uh0; Al = (const __nv_bfloat16*)Ul0;
                ksl0 = (kw - 4) * 4;
            }
            Ah += btile * 16 * USTRIDE;
            Al += btile * 16 * USTRIDE;
            const int ksg0 = kw * 4;
            const __nv_bfloat16* Wh0 = (const __nv_bfloat16*)WhhH;
            const __nv_bfloat16* Wl0 = (const __nv_bfloat16*)WhhL;

            wmma::fill_fragment(acc0, 0.0f);
            wmma::fill_fragment(acc1, 0.0f);
            wmma::fill_fragment(acc2, 0.0f);
            #pragma unroll
            for (int i = 0; i < 4; i++) {
                wmma::load_matrix_sync(fa_h, Ah + (ksl0 + i) * 16, USTRIDE);
                wmma::load_matrix_sync(fa_l, Al + (ksl0 + i) * 16, USTRIDE);
                const int kc = (ksg0 + i) * 16;
                wmma::load_matrix_sync(fb_h, Wh0 + 0 * 16 * WHHS + kc, WHHS);
                wmma::load_matrix_sync(fb_l, Wl0 + 0 * 16 * WHHS + kc, WHHS);
                wmma::mma_sync(acc0, fa_h, fb_h, acc0);
                wmma::mma_sync(acc0, fa_h, fb_l, acc0);
                wmma::mma_sync(acc0, fa_l, fb_h, acc0);
                wmma::load_matrix_sync(fb_h, Wh0 + 1 * 16 * WHHS + kc, WHHS);
                wmma::load_matrix_sync(fb_l, Wl0 + 1 * 16 * WHHS + kc, WHHS);
                wmma::mma_sync(acc1, fa_h, fb_h, acc1);
                wmma::mma_sync(acc1, fa_h, fb_l, acc1);
                wmma::mma_sync(acc1, fa_l, fb_h, acc1);
                wmma::load_matrix_sync(fb_h, Wh0 + 2 * 16 * WHHS + kc, WHHS);
                wmma::load_matrix_sync(fb_l, Wl0 + 2 * 16 * WHHS + kc, WHHS);
                wmma::mma_sync(acc2, fa_h, fb_h, acc2);
                wmma::mma_sync(acc2, fa_h, fb_l, acc2);
                wmma::mma_sync(acc2, fa_l, fb_h, acc2);
            }
            wmma::store_matrix_sync(Dred + (btile * 24 + 0 * 8 + kw) * 256, acc0, 16, wmma::mem_row_major);
            wmma::store_matrix_sync(Dred + (btile * 24 + 1 * 8 + kw) * 256, acc1, 16, wmma::mem_row_major);
            wmma::store_matrix_sync(Dred + (btile * 24 + 2 * 8 + kw) * 256, acc2, 16, wmma::mem_row_major);
        }
        __syncthreads();

        // reduce 8 kw partials + gates + h update (h_old in register)
        {
            float dr = 0.0f, dz = 0.0f, dn = 0.0f;
            #pragma unroll
            for (int k2 = 0; k2 < 8; k2++) {
                dr += Dred[(btl * 24 + k2) * 256 + loc];
                dz += Dred[(btl * 24 + 8 + k2) * 256 + loc];
                dn += Dred[(btl * 24 + 16 + k2) * 256 + loc];
            }
            float r = sigm(xr + dr + bhr);
            float z = sigm(xz + dz + bhz);
            float n = tanhf(xnv + r * (dn + bhn));
            hold = n + z * (hold - n);
            const int gi = (b0 + bb) * HH + j0 + jj;
            g_hsh[wp][gi] = bhi(hold);
            g_hsl[wp][gi] = blo(hold);
            if (t == TT - 1) out[gi] = hold;
        }
        __syncthreads();

        // publish: flag = t+1
        if (tid == 0) {
            __threadfence();
            *((volatile unsigned*)&g_flags[gb][gj]) = (unsigned)(t + 1);
        }
    }
}

extern "C" void kernel_launch(void* const* d_in, const int* in_sizes, int n_in,
                              void* d_out, int out_size) {
    (void)in_sizes; (void)n_in; (void)out_size;
    cudaFuncSetAttribute(gru_persistent_kernel,
                         cudaFuncAttributeMaxDynamicSharedMemorySize, SMEM_BYTES);
    gru_persistent_kernel<<<NCTA, NTHR, SMEM_BYTES>>>(
        (const float*)d_in[0],
        (const float*)d_in[1],
        (const float*)d_in[2],
        (const float*)d_in[3],
        (const float*)d_in[4],
        (float*)d_out);
}

// round 14
// speedup vs baseline: 1.5577x; 1.5577x over previous
#include <cuda_runtime.h>
#include <cuda_bf16.h>
#include <mma.h>
#include <math.h>

// GRU: B=128, T=512, I=256, H=512. out = final h [1,128,512] fp32.
// Persistent kernel, 128 CTAs (4 batch x 32 j), wmma bf16 hi/lo 3-product.
// R10 structure (x staging + chunk-0 mma overlap the inter-CTA wait) with:
//  - producer-flag sync over 32-CTA groups (no atomics in steady state)
//  - h_old carried in registers (no fp32 h array)

using namespace nvcuda;

#define BATCH 128
#define TT    512
#define II    256
#define HH    512
#define GB    4
#define GJ    32
#define BC    32
#define JC    16
#define NCTA  128
#define NSYNC 32
#define NTHR  512

#define WSTRIDE 776     // u16 per fused W row (768+8)
#define USTRIDE 264     // u16 per U row (256+8)

// SMEM byte offsets
#define SM_WH   0
#define SM_WL   (SM_WH  + 48*WSTRIDE*2)
#define SM_UH1  (SM_WL  + 48*WSTRIDE*2)        // buf1 = h[0:256]
#define SM_UL1  (SM_UH1 + 32*USTRIDE*2)
#define SM_UH0  (SM_UL1 + 32*USTRIDE*2)        // buf0 = x / h[256:512]
#define SM_UL0  (SM_UH0 + 32*USTRIDE*2)
#define SM_DRED (SM_UL0 + 32*USTRIDE*2)        // 12 tiles * 256 f32
#define SM_DXN  (SM_DRED + 12*256*4)           // 2 tiles * 256 f32
#define SM_BS   (SM_DXN + 2*256*4)             // 64 f32
#define SMEM_BYTES (SM_BS + 256)               // 231168

__device__ unsigned short g_hsh[2][BATCH*HH];
__device__ unsigned short g_hsl[2][BATCH*HH];
__device__ unsigned short g_xh [(size_t)BATCH*TT*II];
__device__ unsigned short g_xl [(size_t)BATCH*TT*II];
__device__ __align__(128) unsigned int g_flags[GB][32];
__device__ unsigned int   g_count = 0;
__device__ unsigned int   g_phase = 0;

__device__ __forceinline__ float sigm(float x) {
    return 1.0f / (1.0f + __expf(-x));
}
__device__ __forceinline__ unsigned short bhi(float v) {
    return __bfloat16_as_ushort(__float2bfloat16(v));
}
__device__ __forceinline__ unsigned short blo(float v) {
    __nv_bfloat16 h = __float2bfloat16(v);
    return __bfloat16_as_ushort(__float2bfloat16(v - __bfloat162float(h)));
}

extern "C" __global__ void __launch_bounds__(NTHR, 1)
gru_persistent_kernel(const float* __restrict__ x,      // [B, T, I]
                      const float* __restrict__ W_ih,   // [3H, I]
                      const float* __restrict__ W_hh,   // [3H, H]
                      const float* __restrict__ b_ih,   // [3H]
                      const float* __restrict__ b_hh,   // [3H]
                      float* __restrict__ out)          // [1, B, H]
{
    extern __shared__ char smem[];
    unsigned short* Wh  = (unsigned short*)(smem + SM_WH);
    unsigned short* Wl  = (unsigned short*)(smem + SM_WL);
    unsigned short* Uh1 = (unsigned short*)(smem + SM_UH1);
    unsigned short* Ul1 = (unsigned short*)(smem + SM_UL1);
    unsigned short* Uh0 = (unsigned short*)(smem + SM_UH0);
    unsigned short* Ul0 = (unsigned short*)(smem + SM_UL0);
    float* Dred = (float*)(smem + SM_DRED);
    float* Dxn  = (float*)(smem + SM_DXN);
    float* B_s  = (float*)(smem + SM_BS);

    const int tid = threadIdx.x;
    const int bx  = blockIdx.x;
    const int gb  = bx & (GB - 1);
    const int gj  = bx >> 2;
    const int b0  = gb * BC;
    const int j0  = gj * JC;

    // relative-phase base for the (self-cleaning) init barrier
    unsigned base = 0;
    if (tid == 0) base = *((volatile unsigned*)&g_phase);

    // ---- one-time: fused W tile hi/lo (rows 0-15 r, 16-31 z, 32-47 n) ----
    for (int idx = tid; idx < 48 * 768; idx += NTHR) {
        int row = idx / 768;
        int col = idx - row * 768;
        int G = (row < 16) ? j0 + row
              : (row < 32) ? 512 + j0 + (row - 16)
                           : 1024 + j0 + (row - 32);
        float v = (col < II) ? W_ih[G * II + col] : W_hh[G * HH + (col - II)];
        Wh[row * WSTRIDE + col] = bhi(v);
        Wl[row * WSTRIDE + col] = blo(v);
    }
    if (tid < 64) {
        int i = tid & 15;
        float v;
        if (tid < 16)      v = b_ih[j0 + i]       + b_hh[j0 + i];        // r
        else if (tid < 32) v = b_ih[512 + j0 + i] + b_hh[512 + j0 + i];  // z
        else if (tid < 48) v = b_ih[1024 + j0 + i];                      // xn
        else               v = b_hh[1024 + j0 + i];                      // hn
        B_s[tid] = v;
    }

    // ---- pre-phase: split x into hi/lo planes; zero own h0 tile; flags ----
    {
        const size_t total = (size_t)BATCH * TT * II;
        for (size_t i = (size_t)(bx * NTHR + tid) * 8; i < total;
             i += (size_t)NCTA * NTHR * 8) {
            float4 v0 = *(const float4*)(x + i);
            float4 v1 = *(const float4*)(x + i + 4);
            float vv[8] = {v0.x, v0.y, v0.z, v0.w, v1.x, v1.y, v1.z, v1.w};
            unsigned hs[8], ls[8];
            #pragma unroll
            for (int j = 0; j < 8; j++) {
                hs[j] = bhi(vv[j]);
                ls[j] = blo(vv[j]);
            }
            uint4 ph, pl;
            ph.x = hs[0] | (hs[1] << 16); ph.y = hs[2] | (hs[3] << 16);
            ph.z = hs[4] | (hs[5] << 16); ph.w = hs[6] | (hs[7] << 16);
            pl.x = ls[0] | (ls[1] << 16); pl.y = ls[2] | (ls[3] << 16);
            pl.z = ls[4] | (ls[5] << 16); pl.w = ls[6] | (ls[7] << 16);
            *(uint4*)(g_xh + i) = ph;
            *(uint4*)(g_xl + i) = pl;
        }
        for (int i = tid; i < BC * JC; i += NTHR) {
            int b = i >> 4, j = i & 15;
            int gi = (b0 + b) * HH + j0 + j;
            g_hsh[0][gi] = 0;
            g_hsl[0][gi] = 0;
        }
        if (tid == 0) *((volatile unsigned*)&g_flags[gb][gj]) = 0u;
    }

    // init barrier (global, count-based, self-cleaning)
    __syncthreads();
    if (tid == 0) {
        __threadfence();
        if (atomicAdd(&g_count, 1u) == NCTA - 1u) {
            g_count = 0;
            __threadfence();
            *((volatile unsigned*)&g_phase) = base + 1u;
        }
        while ((unsigned)(*((volatile unsigned*)&g_phase) - base) < 1u) {
            __nanosleep(32);
        }
        __threadfence();
    }
    __syncthreads();

    // mma warp roles: w<12 -> (btile, ntile, kh)
    const int w     = tid >> 5;
    const int lane  = tid & 31;
    const int kh    = w & 1;
    const int tau   = w >> 1;
    const int btile = tau / 3;
    const int ntile = tau % 3;

    wmma::fragment<wmma::matrix_a, 16, 16, 16, __nv_bfloat16, wmma::row_major> fa_h, fa_l;
    wmma::fragment<wmma::matrix_b, 16, 16, 16, __nv_bfloat16, wmma::col_major> fb_h, fb_l;
    wmma::fragment<wmma::accumulator, 16, 16, 16, float> facc;

    // staging indices
    const int srow = tid >> 4;          // 0..31
    const int sk16 = (tid & 15) * 16;
    const int sk32 = (tid & 15) * 32;

    // gate-phase mapping (one (b, j) element per thread)
    const int jj  = tid & 15;
    const int bb  = tid >> 4;           // 0..31
    const int gbt = bb >> 4;
    const float bias_r  = B_s[jj];
    const float bias_z  = B_s[16 + jj];
    const float bias_xn = B_s[32 + jj];
    const float bias_hn = B_s[48 + jj];
    const int loc = (bb & 15) * 16 + jj;
    float hold = 0.0f;

    for (int t = 0; t < TT; t++) {
        const int rp = t & 1;
        const int wp = rp ^ 1;

        // ---- stage x(t): plane copy into buf0 ----
        {
            const size_t off = ((size_t)(b0 + srow) * TT + t) * II + sk16;
            const uint4* sh = (const uint4*)(g_xh + off);
            const uint4* sl = (const uint4*)(g_xl + off);
            uint4* dh = (uint4*)(Uh0 + srow * USTRIDE + sk16);
            uint4* dl = (uint4*)(Ul0 + srow * USTRIDE + sk16);
            dh[0] = sh[0]; dh[1] = sh[1];
            dl[0] = sl[0]; dl[1] = sl[1];
        }
        __syncthreads();

        // ---- chunk 0: x projection (independent of peers' h) ----
        if (w < 12) {
            wmma::fill_fragment(facc, 0.0f);
            const __nv_bfloat16* Ah = (const __nv_bfloat16*)(Uh0 + btile * 16 * USTRIDE);
            const __nv_bfloat16* Al = (const __nv_bfloat16*)(Ul0 + btile * 16 * USTRIDE);
            const __nv_bfloat16* Bh = (const __nv_bfloat16*)(Wh + ntile * 16 * WSTRIDE);
            const __nv_bfloat16* Bl = (const __nv_bfloat16*)(Wl + ntile * 16 * WSTRIDE);
            if (ntile < 2) {
                #pragma unroll
                for (int ks = kh * 8; ks < kh * 8 + 8; ks++) {
                    wmma::load_matrix_sync(fa_h, Ah + ks * 16, USTRIDE);
                    wmma::load_matrix_sync(fa_l, Al + ks * 16, USTRIDE);
                    wmma::load_matrix_sync(fb_h, Bh + ks * 16, WSTRIDE);
                    wmma::load_matrix_sync(fb_l, Bl + ks * 16, WSTRIDE);
                    wmma::mma_sync(facc, fa_h, fb_h, facc);
                    wmma::mma_sync(facc, fa_h, fb_l, facc);
                    wmma::mma_sync(facc, fa_l, fb_h, facc);
                }
            } else if (kh == 0) {   // ntile==2: one warp does all 16 ks, stores xn
                #pragma unroll
                for (int ks = 0; ks < 16; ks++) {
                    wmma::load_matrix_sync(fa_h, Ah + ks * 16, USTRIDE);
                    wmma::load_matrix_sync(fa_l, Al + ks * 16, USTRIDE);
                    wmma::load_matrix_sync(fb_h, Bh + ks * 16, WSTRIDE);
                    wmma::load_matrix_sync(fb_l, Bl + ks * 16, WSTRIDE);
                    wmma::mma_sync(facc, fa_h, fb_h, facc);
                    wmma::mma_sync(facc, fa_h, fb_l, facc);
                    wmma::mma_sync(facc, fa_l, fb_h, facc);
                }
                wmma::store_matrix_sync(Dxn + btile * 256, facc, 16, wmma::mem_row_major);
                wmma::fill_fragment(facc, 0.0f);
            }
        }

        // ---- wait: 32 producer flags >= t (warp 0 parallel poll) ----
        if (w == 0) {
            const volatile unsigned* fl = &g_flags[gb][0];
            for (;;) {
                unsigned v = fl[lane];
                if (!__any_sync(0xFFFFFFFFu, v < (unsigned)t)) break;
                __nanosleep(32);
            }
            __threadfence();
        }
        __syncthreads();

        // ---- stage h planes: h[0:256]->buf1, h[256:512]->buf0 ----
        {
            const int goff = (b0 + srow) * HH + sk32;
            const uint4* sh = (const uint4*)(g_hsh[rp] + goff);
            const uint4* sl = (const uint4*)(g_hsl[rp] + goff);
            uint4 *dh, *dl;
            if (sk32 < 256) {
                dh = (uint4*)(Uh1 + srow * USTRIDE + sk32);
                dl = (uint4*)(Ul1 + srow * USTRIDE + sk32);
            } else {
                dh = (uint4*)(Uh0 + srow * USTRIDE + (sk32 - 256));
                dl = (uint4*)(Ul0 + srow * USTRIDE + (sk32 - 256));
            }
            dh[0] = sh[0]; dh[1] = sh[1]; dh[2] = sh[2]; dh[3] = sh[3];
            dl[0] = sl[0]; dl[1] = sl[1]; dl[2] = sl[2]; dl[3] = sl[3];
        }
        __syncthreads();

        // ---- chunks 1 (buf1) + 2 (buf0): h projection ----
        if (w < 12) {
            #pragma unroll
            for (int c = 1; c < 3; c++) {
                const unsigned short* UhB = (c == 1) ? Uh1 : Uh0;
                const unsigned short* UlB = (c == 1) ? Ul1 : Ul0;
                const __nv_bfloat16* Ah = (const __nv_bfloat16*)(UhB + btile * 16 * USTRIDE);
                const __nv_bfloat16* Al = (const __nv_bfloat16*)(UlB + btile * 16 * USTRIDE);
                const __nv_bfloat16* Bh = (const __nv_bfloat16*)(Wh + ntile * 16 * WSTRIDE + c * 256);
                const __nv_bfloat16* Bl = (const __nv_bfloat16*)(Wl + ntile * 16 * WSTRIDE + c * 256);
                #pragma unroll
                for (int ks = kh * 8; ks < kh * 8 + 8; ks++) {
                    wmma::load_matrix_sync(fa_h, Ah + ks * 16, USTRIDE);
                    wmma::load_matrix_sync(fa_l, Al + ks * 16, USTRIDE);
                    wmma::load_matrix_sync(fb_h, Bh + ks * 16, WSTRIDE);
                    wmma::load_matrix_sync(fb_l, Bl + ks * 16, WSTRIDE);
                    wmma::mma_sync(facc, fa_h, fb_h, facc);
                    wmma::mma_sync(facc, fa_h, fb_l, facc);
                    wmma::mma_sync(facc, fa_l, fb_h, facc);
                }
            }
            wmma::store_matrix_sync(Dred + ((btile * 3 + ntile) * 2 + kh) * 256,
                                    facc, 16, wmma::mem_row_major);
        }
        __syncthreads();

        // ---- gates + h update (h_old in register) ----
        {
            float dr  = Dred[((gbt * 3 + 0) * 2 + 0) * 256 + loc]
                      + Dred[((gbt * 3 + 0) * 2 + 1) * 256 + loc];
            float dz  = Dred[((gbt * 3 + 1) * 2 + 0) * 256 + loc]
                      + Dred[((gbt * 3 + 1) * 2 + 1) * 256 + loc];
            float dhn = Dred[((gbt * 3 + 2) * 2 + 0) * 256 + loc]
                      + Dred[((gbt * 3 + 2) * 2 + 1) * 256 + loc];
            float dxn = Dxn[gbt * 256 + loc];
            float r = sigm(dr + bias_r);
            float z = sigm(dz + bias_z);
            float n = tanhf(dxn + bias_xn + r * (dhn + bias_hn));
            hold = n + z * (hold - n);
            const int gi = (b0 + bb) * HH + j0 + jj;
            g_hsh[wp][gi] = bhi(hold);
            g_hsl[wp][gi] = blo(hold);
            if (t == TT - 1) out[gi] = hold;
        }
        __syncthreads();

        // ---- publish: flag = t+1 ----
        if (tid == 0) {
            __threadfence();
            *((volatile unsigned*)&g_flags[gb][gj]) = (unsigned)(t + 1);
        }
    }
}

extern "C" void kernel_launch(void* const* d_in, const int* in_sizes, int n_in,
                              void* d_out, int out_size) {
    (void)in_sizes; (void)n_in; (void)out_size;
    cudaFuncSetAttribute(gru_persistent_kernel,
                         cudaFuncAttributeMaxDynamicSharedMemorySize, SMEM_BYTES);
    gru_persistent_kernel<<<NCTA, NTHR, SMEM_BYTES>>>(
        (const float*)d_in[0],
        (const float*)d_in[1],
        (const float*)d_in[2],
        (const float*)d_in[3],
        (const float*)d_in[4],
        (float*)d_out);
}